// round 4
// baseline (speedup 1.0000x reference)
#include <cuda_runtime.h>
#include <cuda_bf16.h>
#include <cstdint>

#define N_ROWS   32768
#define HDIM     1024
#define N_MOTIF  128
#define N_CLASS  16
#define K2       32
#define EPS_C    1e-4f
#define TAU_C    0.99f

// ---------------- device scratch ----------------
__device__ float g_distT[(size_t)N_MOTIF * N_ROWS];   // 16 MB distance transposed [motif][row]
__device__ int   g_y[N_ROWS];
__device__ float g_loss_partial[256];

#define NEG_INF __int_as_float(0xff800000)

__device__ __forceinline__ uint32_t smem_u32(const void* p) {
    uint32_t a;
    asm("{ .reg .u64 t; cvta.to.shared.u64 t, %1; cvt.u32.u64 %0, t; }" : "=r"(a) : "l"(p));
    return a;
}
__device__ __forceinline__ float rcp_newton(float x) {
    float y = __uint_as_float(0x7EF311C3u - __float_as_uint(x));
    y = y * fmaf(-x, y, 2.f);
    y = y * fmaf(-x, y, 2.f);
    y = y * fmaf(-x, y, 2.f);
    return y;
}
__device__ __forceinline__ uint32_t f2bf2(float lo, float hi) {
    __nv_bfloat162 h = __floats2bfloat162_rn(lo, hi);
    return *(uint32_t*)&h;
}
#define LDSM_X4(r0, r1, r2, r3, addr) \
    asm volatile("ldmatrix.sync.aligned.m8n8.x4.shared.b16 {%0,%1,%2,%3}, [%4];" \
        : "=r"(r0), "=r"(r1), "=r"(r2), "=r"(r3) : "r"(addr))

// ---------------- y conversion (int64 or int32 storage) ----------------
__global__ void k_yconv(const int* __restrict__ yraw) {
    __shared__ int is64;
    int t = threadIdx.x;
    if (t == 0) {
        int f = 1;
        for (int i = 0; i < 32; i++)
            if (yraw[2 * i + 1] != 0) { f = 0; break; }
        is64 = f;
    }
    __syncthreads();
    if (is64) { for (int i = t; i < N_ROWS; i += 256) g_y[i] = yraw[2 * i]; }
    else      { for (int i = t; i < N_ROWS; i += 256) g_y[i] = yraw[i]; }
}

// ---------------- fused GEMM + distance + loss-row-stats ----------------
// 256 threads (8 warps 4x2), tile 128 rows x 128 motifs, KC=16 per chunk, 64 chunks,
// double-buffered smem, ldmatrix fragment loads, legacy bf16 mma.sync.
#define KC 16
#define KP 24   // padded stride: 48B/row -> 8-row ldmatrix phases cover all 32 banks

struct __align__(16) SmemU {
    union {
        struct {
            __nv_bfloat16 zA[2][128][KP];
            __nv_bfloat16 mB[2][128][KP];
        } ab;
        float xp[64][129];
    } u;
};

__global__ __launch_bounds__(256, 2)
void k_gemm(const float* __restrict__ z, const float* __restrict__ Mv) {
    __shared__ SmemU sm;
    __shared__ float zn_s[128], mn_s[128], loss_s[128];

    const int t    = threadIdx.x;
    const int lane = t & 31;
    const int w    = t >> 5;
    const int wm   = w >> 1;   // 0..3
    const int wn   = w & 1;    // 0..1
    const int r0   = blockIdx.x * 128;

    // loader: threads 0-127 -> z row t; threads 128-255 -> motif row t-128
    const int lrow = t & 127;
    const bool isZ = (t < 128);
    const float* src = isZ ? (z + (size_t)(r0 + lrow) * HDIM)
                           : (Mv + (size_t)lrow * HDIM);

    float acc[2][8][4];
#pragma unroll
    for (int a = 0; a < 2; a++)
#pragma unroll
        for (int b = 0; b < 8; b++)
#pragma unroll
            for (int c = 0; c < 4; c++) acc[a][b][c] = 0.f;

    float sq = 0.f;

    // ldmatrix addresses (per lane), both buffers
    uint32_t aAddr[2][2], bAddr[2][4];
    {
        int arow = wm * 32 + (lane & 15);
        int acol = (lane < 16) ? 0 : 8;
#pragma unroll
        for (int buf = 0; buf < 2; buf++) {
            aAddr[buf][0] = smem_u32(&sm.u.ab.zA[buf][arow][acol]);
            aAddr[buf][1] = smem_u32(&sm.u.ab.zA[buf][arow + 16][acol]);
            int g = lane >> 3;
            int bk = (g & 1) * 8;
            int bnbase = (g >= 2) ? 8 : 0;
#pragma unroll
            for (int pair = 0; pair < 4; pair++) {
                int n = wn * 64 + pair * 16 + bnbase + (lane & 7);
                bAddr[buf][pair] = smem_u32(&sm.u.ab.mB[buf][n][bk]);
            }
        }
    }

    // prologue: chunk 0 into buf 0
    float4 v[4];
#pragma unroll
    for (int j = 0; j < 4; j++) v[j] = *(const float4*)(src + 4 * j);
    {
#pragma unroll
        for (int j = 0; j < 4; j++) {
            sq = fmaf(v[j].x, v[j].x, sq); sq = fmaf(v[j].y, v[j].y, sq);
            sq = fmaf(v[j].z, v[j].z, sq); sq = fmaf(v[j].w, v[j].w, sq);
        }
        uint4 u0, u1;
        u0.x = f2bf2(v[0].x, v[0].y); u0.y = f2bf2(v[0].z, v[0].w);
        u0.z = f2bf2(v[1].x, v[1].y); u0.w = f2bf2(v[1].z, v[1].w);
        u1.x = f2bf2(v[2].x, v[2].y); u1.y = f2bf2(v[2].z, v[2].w);
        u1.z = f2bf2(v[3].x, v[3].y); u1.w = f2bf2(v[3].z, v[3].w);
        __nv_bfloat16* d = isZ ? &sm.u.ab.zA[0][lrow][0] : &sm.u.ab.mB[0][lrow][0];
        *(uint4*)d = u0;
        *(uint4*)(d + 8) = u1;
    }

    for (int ch = 0; ch < 64; ch++) {
        const int buf = ch & 1;
        __syncthreads();

        // issue next chunk's global loads (latency hidden under mma)
        if (ch < 63) {
            const float* s2 = src + (ch + 1) * KC;
#pragma unroll
            for (int j = 0; j < 4; j++) v[j] = *(const float4*)(s2 + 4 * j);
        }

        // fragments via ldmatrix
        uint32_t af[2][4];
        LDSM_X4(af[0][0], af[0][1], af[0][2], af[0][3], aAddr[buf][0]);
        LDSM_X4(af[1][0], af[1][1], af[1][2], af[1][3], aAddr[buf][1]);
        uint32_t bf[8][2];
#pragma unroll
        for (int pair = 0; pair < 4; pair++)
            LDSM_X4(bf[2 * pair][0], bf[2 * pair][1],
                    bf[2 * pair + 1][0], bf[2 * pair + 1][1], bAddr[buf][pair]);

#pragma unroll
        for (int mt = 0; mt < 2; mt++)
#pragma unroll
            for (int nt = 0; nt < 8; nt++) {
                asm volatile(
                    "mma.sync.aligned.m16n8k16.row.col.f32.bf16.bf16.f32 "
                    "{%0,%1,%2,%3},{%4,%5,%6,%7},{%8,%9},{%0,%1,%2,%3};"
                    : "+f"(acc[mt][nt][0]), "+f"(acc[mt][nt][1]),
                      "+f"(acc[mt][nt][2]), "+f"(acc[mt][nt][3])
                    : "r"(af[mt][0]), "r"(af[mt][1]), "r"(af[mt][2]), "r"(af[mt][3]),
                      "r"(bf[nt][0]), "r"(bf[nt][1]));
            }

        // convert + store next chunk into the other buffer
        if (ch < 63) {
#pragma unroll
            for (int j = 0; j < 4; j++) {
                sq = fmaf(v[j].x, v[j].x, sq); sq = fmaf(v[j].y, v[j].y, sq);
                sq = fmaf(v[j].z, v[j].z, sq); sq = fmaf(v[j].w, v[j].w, sq);
            }
            uint4 u0, u1;
            u0.x = f2bf2(v[0].x, v[0].y); u0.y = f2bf2(v[0].z, v[0].w);
            u0.z = f2bf2(v[1].x, v[1].y); u0.w = f2bf2(v[1].z, v[1].w);
            u1.x = f2bf2(v[2].x, v[2].y); u1.y = f2bf2(v[2].z, v[2].w);
            u1.z = f2bf2(v[3].x, v[3].y); u1.w = f2bf2(v[3].z, v[3].w);
            int nb = (ch + 1) & 1;
            __nv_bfloat16* d = isZ ? &sm.u.ab.zA[nb][lrow][0] : &sm.u.ab.mB[nb][lrow][0];
            *(uint4*)d = u0;
            *(uint4*)(d + 8) = u1;
        }
    }

    // row norms
    if (isZ) zn_s[lrow] = sq; else mn_s[lrow] = sq;

    // epilogue: two halves of 64 rows through smem staging
    const int rA = lane >> 2;
    for (int half = 0; half < 2; half++) {
        __syncthreads();
        if ((wm >> 1) == half) {
            int mrel = wm - half * 2;
#pragma unroll
            for (int mt = 0; mt < 2; mt++)
#pragma unroll
                for (int nt = 0; nt < 8; nt++)
#pragma unroll
                    for (int r = 0; r < 4; r++) {
                        int row = mrel * 32 + mt * 16 + rA + 8 * (r >> 1);
                        int col = wn * 64 + nt * 8 + 2 * (lane & 3) + (r & 1);
                        sm.u.xp[row][col] = acc[mt][nt][r];
                    }
        }
        __syncthreads();

        // loss row stats: 4 threads per row, 32 cols each
        {
            int rloc = t >> 2, q = t & 3;
            int grow = r0 + half * 64 + rloc;
            int ycls = g_y[grow];
            float znv = zn_s[half * 64 + rloc];
            float pmax = NEG_INF, nsum = 0.f;
#pragma unroll 8
            for (int c = q * 32; c < q * 32 + 32; c++) {
                float d  = fmaf(-2.f, sm.u.xp[rloc][c], znv + mn_s[c]);
                float x  = d + EPS_C;
                float dl = (1.f - EPS_C) * rcp_newton(x);
                float rr = 1.f + dl;
                float r2 = rr * rr;
                float s  = r2 * r2 * rr;           // ((d+1)/(d+eps))^5
                if ((c >> 3) == ycls) pmax = fmaxf(pmax, s);
                else nsum += s;
            }
            nsum += __shfl_xor_sync(0xffffffffu, nsum, 1);
            nsum += __shfl_xor_sync(0xffffffffu, nsum, 2);
            pmax = fmaxf(pmax, __shfl_xor_sync(0xffffffffu, pmax, 1));
            pmax = fmaxf(pmax, __shfl_xor_sync(0xffffffffu, pmax, 2));
            if (q == 0) loss_s[half * 64 + rloc] = log1pf(nsum / pmax);
        }

        // transposed distance write: coalesced down columns
        {
            int cc  = t >> 6;
            int rr2 = t & 63;
            float znv2 = zn_s[half * 64 + rr2];
#pragma unroll
            for (int c0 = 0; c0 < 128; c0 += 4) {
                int c = c0 + cc;
                float d = fmaf(-2.f, sm.u.xp[rr2][c], znv2 + mn_s[c]);
                g_distT[(size_t)c * N_ROWS + r0 + half * 64 + rr2] = d;
            }
        }
    }

    __syncthreads();
    for (int s = 64; s > 0; s >>= 1) {
        if (t < s) loss_s[t] += loss_s[t + s];
        __syncthreads();
    }
    if (t == 0) g_loss_partial[blockIdx.x] = loss_s[0];
}

// ---------------- top-k + motif update ----------------
#define CAP 6080

__global__ __launch_bounds__(256)
void k_topk(const float* __restrict__ z, const float* __restrict__ M,
            float* __restrict__ out, int moff, int writeM) {
    __shared__ float sv[CAP];
    __shared__ int   si[CAP];
    __shared__ int   cnt;
    __shared__ float wv[8];
    __shared__ int   wi[8], wp[8];
    __shared__ int   selIdx[K2];

    const int t    = threadIdx.x;
    const int lane = t & 31;
    const int j    = blockIdx.x;
    const int cls  = j >> 3;

    if (t == 0) cnt = 0;
    __syncthreads();

    const float* dcol = g_distT + (size_t)j * N_ROWS;
    for (int i = t; i < N_ROWS; i += 256) {
        float v = dcol[i];
        bool m = (g_y[i] == cls);
        unsigned msk = __ballot_sync(0xffffffffu, m);
        if (msk) {
            int leader = __ffs(msk) - 1;
            int base = 0;
            if (lane == leader) base = atomicAdd(&cnt, __popc(msk));
            base = __shfl_sync(0xffffffffu, base, leader);
            if (m) {
                int p = base + __popc(msk & ((1u << lane) - 1u));
                if (p < CAP) { sv[p] = v; si[p] = i; }
            }
        }
    }
    __syncthreads();
    const int n = min(cnt, CAP);

    for (int k = 0; k < K2; k++) {
        float bv = NEG_INF; int bi = 0x7fffffff; int bp = -1;
        for (int p = t; p < n; p += 256) {
            float v = sv[p]; int ii = si[p];
            if (v > bv || (v == bv && ii < bi)) { bv = v; bi = ii; bp = p; }
        }
#pragma unroll
        for (int o = 16; o > 0; o >>= 1) {
            float ov = __shfl_xor_sync(0xffffffffu, bv, o);
            int   oi = __shfl_xor_sync(0xffffffffu, bi, o);
            int   op = __shfl_xor_sync(0xffffffffu, bp, o);
            if (ov > bv || (ov == bv && oi < bi)) { bv = ov; bi = oi; bp = op; }
        }
        if (lane == 0) { wv[t >> 5] = bv; wi[t >> 5] = bi; wp[t >> 5] = bp; }
        __syncthreads();
        if (t == 0) {
            bv = wv[0]; bi = wi[0]; bp = wp[0];
            for (int q = 1; q < 8; q++)
                if (wv[q] > bv || (wv[q] == bv && wi[q] < bi)) { bv = wv[q]; bi = wi[q]; bp = wp[q]; }
            selIdx[k] = bi;
            if (bp >= 0) sv[bp] = NEG_INF;
        }
        __syncthreads();
    }

    float a0 = 0.f, a1 = 0.f, a2 = 0.f, a3 = 0.f;
#pragma unroll 4
    for (int k = 0; k < K2; k++) {
        const float* zr = z + (size_t)selIdx[k] * HDIM;
        a0 += zr[t]; a1 += zr[t + 256]; a2 += zr[t + 512]; a3 += zr[t + 768];
    }
    if (writeM) {
        const float* mr = M + (size_t)j * HDIM;
        float* o = out + moff + (size_t)j * HDIM;
        const float invk = 1.f / (float)K2;
        const float om = 1.f - TAU_C;
        o[t]       = TAU_C * mr[t]       + om * (a0 * invk);
        o[t + 256] = TAU_C * mr[t + 256] + om * (a1 * invk);
        o[t + 512] = TAU_C * mr[t + 512] + om * (a2 * invk);
        o[t + 768] = TAU_C * mr[t + 768] + om * (a3 * invk);
    }
}

// ---------------- final loss reduction ----------------
__global__ void k_lossfin(float* __restrict__ out, int idx) {
    __shared__ float s[256];
    int t = threadIdx.x;
    s[t] = g_loss_partial[t];
    __syncthreads();
    for (int d = 128; d > 0; d >>= 1) {
        if (t < d) s[t] += s[t + d];
        __syncthreads();
    }
    if (t == 0) out[idx] = s[0] * (1.f / (float)N_ROWS);
}

// ---------------- entry ----------------
extern "C" void kernel_launch(void* const* d_in, const int* in_sizes, int n_in,
                              void* d_out, int out_size) {
    const float* z = (const float*)d_in[0];
    const float* M = (const float*)d_in[1];
    const int*   y = (const int*)d_in[2];
    float* out = (float*)d_out;

    int moff, writeM, writeLoss;
    if (out_size >= N_MOTIF * HDIM + 1)  { moff = 1; writeM = 1; writeLoss = 1; }
    else if (out_size >= N_MOTIF * HDIM) { moff = 0; writeM = 1; writeLoss = 0; }
    else                                 { moff = 0; writeM = 0; writeLoss = 1; }

    k_yconv<<<1, 256>>>(y);
    k_gemm<<<N_ROWS / 128, 256>>>(z, M);
    k_topk<<<N_MOTIF, 256>>>(z, M, out, moff, writeM);
    if (writeLoss) k_lossfin<<<1, 256>>>(out, 0);
}

// round 5
// speedup vs baseline: 1.6925x; 1.6925x over previous
#include <cuda_runtime.h>
#include <cuda_bf16.h>
#include <cstdint>

#define N_ROWS   32768
#define HDIM     1024
#define N_MOTIF  128
#define N_CLASS  16
#define K2       32
#define EPS_C    1e-4f
#define TAU_C    0.99f

#define NTILES   256
#define SPT      32                       // slots per tile per class
#define SPC      (NTILES * SPT)           // 8192 slots per class

// ---------------- device scratch ----------------
__device__ float g_cval[(size_t)N_CLASS * 8 * SPC];  // 4 MB  [class][motif-in-class][slot]
__device__ int   g_cidx[(size_t)N_CLASS * SPC];      // 512 KB [class][slot]
__device__ int   g_bcnt[N_CLASS * NTILES];           // per-tile per-class counts (fully rewritten each run)
__device__ float g_loss_partial[128];

#define NEG_INF __int_as_float(0xff800000)

__device__ __forceinline__ uint32_t smem_u32(const void* p) {
    uint32_t a;
    asm("{ .reg .u64 t; cvta.to.shared.u64 t, %1; cvt.u32.u64 %0, t; }" : "=r"(a) : "l"(p));
    return a;
}
__device__ __forceinline__ float rcp_newton(float x) {
    float y = __uint_as_float(0x7EF311C3u - __float_as_uint(x));
    y = y * fmaf(-x, y, 2.f);
    y = y * fmaf(-x, y, 2.f);
    y = y * fmaf(-x, y, 2.f);
    return y;
}
__device__ __forceinline__ uint32_t f2bf2(float lo, float hi) {
    __nv_bfloat162 h = __floats2bfloat162_rn(lo, hi);
    return *(uint32_t*)&h;
}
#define LDSM_X4(r0, r1, r2, r3, addr) \
    asm volatile("ldmatrix.sync.aligned.m8n8.x4.shared.b16 {%0,%1,%2,%3}, [%4];" \
        : "=r"(r0), "=r"(r1), "=r"(r2), "=r"(r3) : "r"(addr))

// ---------------- smem layout for k_gemm (dynamic) ----------------
#define KP      24          // padded bf16 row stride (48B): ldmatrix phases conflict-free
#define XPS     129
#define SM_AB   0           // 2 bufs x 256 rows x 24 bf16 = 24576 B  (union with XP)
#define SM_XP   0           // 128 x 129 f32 = 66048 B
#define SM_P    66048
#define SM_YC   (SM_P)          // 128 int
#define SM_ZN   (SM_P + 512)    // 128 f32
#define SM_MN   (SM_P + 1024)   // 128 f32
#define SM_PM   (SM_P + 1536)   // 4 x 128 f32
#define SM_NS   (SM_P + 3584)   // 4 x 128 f32
#define SM_LOSS (SM_P + 5632)   // 128 f32
#define SM_SCNT (SM_P + 6144)   // 16 int
#define SM_MISC (SM_P + 6208)   // [0]=blk_loss f32, [1]=is64 int
#define SMEMB   (SM_P + 6272)

// ---------------- fused GEMM + distance + loss + candidate emit ----------------
// 512 threads = 16 warps (4x4). Block tile 128x128, per-warp 32x32 (acc 32 regs).
// Each block processes tiles {blockIdx.x, blockIdx.x+128} -> exactly 1 wave on 148 SMs.
__global__ __launch_bounds__(512, 1)
void k_gemm(const float* __restrict__ z, const float* __restrict__ Mv,
            const int* __restrict__ yraw) {
    extern __shared__ char dsm[];
    __nv_bfloat16 (*sAB)[256][KP] = (__nv_bfloat16(*)[256][KP])(dsm + SM_AB);
    float (*xp)[XPS]   = (float(*)[XPS])(dsm + SM_XP);
    int*   yc_s  = (int*)  (dsm + SM_YC);
    float* zn_s  = (float*)(dsm + SM_ZN);
    float* mn_s  = (float*)(dsm + SM_MN);
    float* pm_s  = (float*)(dsm + SM_PM);
    float* ns_s  = (float*)(dsm + SM_NS);
    float* loss_s= (float*)(dsm + SM_LOSS);
    int*   scnt  = (int*)  (dsm + SM_SCNT);
    float* blk_loss = (float*)(dsm + SM_MISC);
    int*   is64p    = (int*)  (dsm + SM_MISC + 4);

    const int t    = threadIdx.x;
    const int lane = t & 31;
    const int w    = t >> 5;
    const int wm   = w >> 2;    // 0..3 (M)
    const int wn   = w & 3;     // 0..3 (N)

    // staging: 2 threads per row, 8 floats each; rows 0-127 = z, 128-255 = M
    const int srow = t >> 1;
    const int half = t & 1;
    const bool isZ = (srow < 128);

    if (t == 0) {
        *blk_loss = 0.f;
        int f = 1;
        for (int i = 0; i < 32; i++)
            if (yraw[2 * i + 1] != 0) { f = 0; break; }
        *is64p = f;
    }

    // ldmatrix addresses (both buffers), computed once
    uint32_t aAddr[2][2], bAddr[2][2];
    {
        int arow = wm * 32 + (lane & 15);
        int acol = (lane < 16) ? 0 : 8;
        int g    = lane >> 3;
        int bk   = (g & 1) * 8;
        int bnb  = (g >= 2) ? 8 : 0;
#pragma unroll
        for (int buf = 0; buf < 2; buf++) {
            aAddr[buf][0] = smem_u32(&sAB[buf][arow][acol]);
            aAddr[buf][1] = smem_u32(&sAB[buf][arow + 16][acol]);
#pragma unroll
            for (int pair = 0; pair < 2; pair++) {
                int n = wn * 32 + pair * 16 + bnb + (lane & 7);
                bAddr[buf][pair] = smem_u32(&sAB[buf][128 + n][bk]);
            }
        }
    }
    __syncthreads();
    const int is64 = *is64p;

    for (int tile = 0; tile < 2; tile++) {
        const int tileIdx = blockIdx.x + tile * 128;
        const int r0 = tileIdx * 128;

        __syncthreads();   // previous epilogue fully done before AB reuse
        if (t < 16)  scnt[t] = 0;
        if (t < 128) yc_s[t] = is64 ? yraw[2 * (r0 + t)] : yraw[r0 + t];

        const float* src = isZ ? (z  + (size_t)(r0 + srow) * HDIM + half * 8)
                               : (Mv + (size_t)(srow - 128) * HDIM + half * 8);

        float acc[2][4][4];
#pragma unroll
        for (int a = 0; a < 2; a++)
#pragma unroll
            for (int b = 0; b < 4; b++)
#pragma unroll
                for (int c = 0; c < 4; c++) acc[a][b][c] = 0.f;
        float sq = 0.f;

        // prologue: chunk 0 -> buf 0
        float4 v0 = *(const float4*)(src);
        float4 v1 = *(const float4*)(src + 4);
        {
            sq = fmaf(v0.x, v0.x, sq); sq = fmaf(v0.y, v0.y, sq);
            sq = fmaf(v0.z, v0.z, sq); sq = fmaf(v0.w, v0.w, sq);
            sq = fmaf(v1.x, v1.x, sq); sq = fmaf(v1.y, v1.y, sq);
            sq = fmaf(v1.z, v1.z, sq); sq = fmaf(v1.w, v1.w, sq);
            uint4 u;
            u.x = f2bf2(v0.x, v0.y); u.y = f2bf2(v0.z, v0.w);
            u.z = f2bf2(v1.x, v1.y); u.w = f2bf2(v1.z, v1.w);
            *(uint4*)&sAB[0][srow][half * 8] = u;
        }

        for (int ch = 0; ch < 64; ch++) {
            const int buf = ch & 1;
            __syncthreads();

            if (ch < 63) {
                const float* s2 = src + (ch + 1) * 16;
                v0 = *(const float4*)(s2);
                v1 = *(const float4*)(s2 + 4);
            }

            uint32_t af[2][4];
            LDSM_X4(af[0][0], af[0][1], af[0][2], af[0][3], aAddr[buf][0]);
            LDSM_X4(af[1][0], af[1][1], af[1][2], af[1][3], aAddr[buf][1]);
            uint32_t bf[4][2];
            LDSM_X4(bf[0][0], bf[0][1], bf[1][0], bf[1][1], bAddr[buf][0]);
            LDSM_X4(bf[2][0], bf[2][1], bf[3][0], bf[3][1], bAddr[buf][1]);

#pragma unroll
            for (int mt = 0; mt < 2; mt++)
#pragma unroll
                for (int nt = 0; nt < 4; nt++) {
                    asm volatile(
                        "mma.sync.aligned.m16n8k16.row.col.f32.bf16.bf16.f32 "
                        "{%0,%1,%2,%3},{%4,%5,%6,%7},{%8,%9},{%0,%1,%2,%3};"
                        : "+f"(acc[mt][nt][0]), "+f"(acc[mt][nt][1]),
                          "+f"(acc[mt][nt][2]), "+f"(acc[mt][nt][3])
                        : "r"(af[mt][0]), "r"(af[mt][1]), "r"(af[mt][2]), "r"(af[mt][3]),
                          "r"(bf[nt][0]), "r"(bf[nt][1]));
                }

            if (ch < 63) {
                sq = fmaf(v0.x, v0.x, sq); sq = fmaf(v0.y, v0.y, sq);
                sq = fmaf(v0.z, v0.z, sq); sq = fmaf(v0.w, v0.w, sq);
                sq = fmaf(v1.x, v1.x, sq); sq = fmaf(v1.y, v1.y, sq);
                sq = fmaf(v1.z, v1.z, sq); sq = fmaf(v1.w, v1.w, sq);
                uint4 u;
                u.x = f2bf2(v0.x, v0.y); u.y = f2bf2(v0.z, v0.w);
                u.z = f2bf2(v1.x, v1.y); u.w = f2bf2(v1.z, v1.w);
                *(uint4*)&sAB[buf ^ 1][srow][half * 8] = u;
            }
        }

        // row norms: combine half-row partials (adjacent lanes, same warp)
        {
            float o = __shfl_xor_sync(0xffffffffu, sq, 1);
            float tot = sq + o;
            if (half == 0) {
                if (isZ) zn_s[srow] = tot;
                else     mn_s[srow - 128] = tot;
            }
        }
        __syncthreads();   // MMA reads of AB done -> safe to overwrite as xp

        // stage acc -> xp[128][129]
        {
            const int rA = lane >> 2;
#pragma unroll
            for (int mt = 0; mt < 2; mt++)
#pragma unroll
                for (int nt = 0; nt < 4; nt++)
#pragma unroll
                    for (int r = 0; r < 4; r++) {
                        int row = wm * 32 + mt * 16 + rA + 8 * (r >> 1);
                        int col = wn * 32 + nt * 8 + 2 * (lane & 3) + (r & 1);
                        xp[row][col] = acc[mt][nt][r];
                    }
        }
        __syncthreads();

        // stats + candidates: thread t -> row=t&127, q=t>>7 handles cols [q*32, q*32+32)
        {
            const int row = t & 127;
            const int q   = t >> 7;
            const int c   = yc_s[row];
            const float znv = zn_s[row];
            float pmax = NEG_INF, nsum = 0.f;
#pragma unroll 8
            for (int i = 0; i < 32; i++) {
                int col = q * 32 + i;
                float d  = fmaf(-2.f, xp[row][col], znv + mn_s[col]);
                float x  = d + EPS_C;
                float dl = (1.f - EPS_C) * rcp_newton(x);
                float rr = 1.f + dl;
                float r2 = rr * rr;
                float s  = r2 * r2 * rr;           // ((d+1)/(d+eps))^5
                if ((col >> 3) == c) pmax = fmaxf(pmax, s);
                else nsum += s;
            }
            pm_s[q * 128 + row] = pmax;
            ns_s[q * 128 + row] = nsum;

            if (q == 0) {
                int rank = atomicAdd(&scnt[c], 1);
                if (rank < SPT) {
                    int slot = tileIdx * SPT + rank;
                    g_cidx[c * SPC + slot] = r0 + row;
#pragma unroll
                    for (int m = 0; m < 8; m++) {
                        int col = 8 * c + m;
                        float d = fmaf(-2.f, xp[row][col], znv + mn_s[col]);
                        g_cval[(size_t)((c << 3) + m) * SPC + slot] = d;
                    }
                }
            }
        }
        __syncthreads();

        if (t < 128) {
            float P = fmaxf(fmaxf(pm_s[t], pm_s[128 + t]),
                            fmaxf(pm_s[256 + t], pm_s[384 + t]));
            float S = (ns_s[t] + ns_s[128 + t]) + (ns_s[256 + t] + ns_s[384 + t]);
            loss_s[t] = log1pf(S / P);
        }
        if (t < 16) g_bcnt[t * NTILES + tileIdx] = min(scnt[t], SPT);
        __syncthreads();
        for (int s = 64; s > 0; s >>= 1) {
            if (t < s) loss_s[t] += loss_s[t + s];
            __syncthreads();
        }
        if (t == 0) *blk_loss += loss_s[0];
    }

    if (t == 0) g_loss_partial[blockIdx.x] = *blk_loss;
}

// ---------------- top-k over pre-compacted candidates + motif update + loss ----------------
#define CAPC 2560   // class size ~2048 +/- 44; +11 sigma margin

__global__ __launch_bounds__(256)
void k_topk(const float* __restrict__ z, const float* __restrict__ M,
            float* __restrict__ out, int moff, int writeM, int writeLoss) {
    __shared__ float sv[CAPC];
    __shared__ int   si[CAPC];
    __shared__ int   bc[256], pre[256];
    __shared__ int   wsum[8], wscan[8];
    __shared__ float wv[8];
    __shared__ int   wi[8], wp[8];
    __shared__ int   selIdx[K2];
    __shared__ float lred[128];

    const int t    = threadIdx.x;
    const int lane = t & 31;
    const int w    = t >> 5;
    const int j    = blockIdx.x;
    const int c    = j >> 3;
    const int m    = j & 7;

    // segment counts + prefix sum (warp scan + warp-total scan)
    int cnt = g_bcnt[c * NTILES + t];
    bc[t] = cnt;
    int v = cnt;
#pragma unroll
    for (int o = 1; o < 32; o <<= 1) {
        int n = __shfl_up_sync(0xffffffffu, v, o);
        if (lane >= o) v += n;
    }
    if (lane == 31) wsum[w] = v;
    __syncthreads();
    if (t < 8) {
        int s = wsum[t];
#pragma unroll
        for (int o = 1; o < 8; o <<= 1) {
            int n = __shfl_up_sync(0xffu, s, o);
            if ((t & 7) >= o) s += n;
        }
        wscan[t] = s;
    }
    __syncthreads();
    int excl = v - cnt + (w > 0 ? wscan[w - 1] : 0);
    pre[t] = excl;
    const int n_total = wscan[7];
    __syncthreads();

    // gather candidates into compact smem arrays
    {
        const float* cvp = g_cval + (size_t)((c << 3) + m) * SPC + t * SPT;
        const int*   cip = g_cidx + (size_t)c * SPC + t * SPT;
        int off = pre[t];
        for (int i = 0; i < cnt; i++) {
            if (off + i < CAPC) { sv[off + i] = cvp[i]; si[off + i] = cip[i]; }
        }
    }
    __syncthreads();
    const int n = min(n_total, CAPC);

    // 32 deterministic argmax extractions (value desc, index asc tie-break)
    for (int k = 0; k < K2; k++) {
        float bvv = NEG_INF; int bi = 0x7fffffff; int bp = -1;
        for (int p = t; p < n; p += 256) {
            float vv = sv[p]; int ii = si[p];
            if (vv > bvv || (vv == bvv && ii < bi)) { bvv = vv; bi = ii; bp = p; }
        }
#pragma unroll
        for (int o = 16; o > 0; o >>= 1) {
            float ov = __shfl_xor_sync(0xffffffffu, bvv, o);
            int   oi = __shfl_xor_sync(0xffffffffu, bi, o);
            int   op = __shfl_xor_sync(0xffffffffu, bp, o);
            if (ov > bvv || (ov == bvv && oi < bi)) { bvv = ov; bi = oi; bp = op; }
        }
        if (lane == 0) { wv[w] = bvv; wi[w] = bi; wp[w] = bp; }
        __syncthreads();
        if (t == 0) {
            bvv = wv[0]; bi = wi[0]; bp = wp[0];
            for (int q = 1; q < 8; q++)
                if (wv[q] > bvv || (wv[q] == bvv && wi[q] < bi)) { bvv = wv[q]; bi = wi[q]; bp = wp[q]; }
            selIdx[k] = (bp >= 0) ? bi : 0;
            if (bp >= 0) sv[bp] = NEG_INF;
        }
        __syncthreads();
    }

    // gather-mean of K2 z-rows + EMA blend
    float a0 = 0.f, a1 = 0.f, a2 = 0.f, a3 = 0.f;
#pragma unroll 4
    for (int k = 0; k < K2; k++) {
        const float* zr = z + (size_t)selIdx[k] * HDIM;
        a0 += zr[t]; a1 += zr[t + 256]; a2 += zr[t + 512]; a3 += zr[t + 768];
    }
    if (writeM) {
        const float* mr = M + (size_t)j * HDIM;
        float* o = out + moff + (size_t)j * HDIM;
        const float invk = 1.f / (float)K2;
        const float om = 1.f - TAU_C;
        o[t]       = TAU_C * mr[t]       + om * (a0 * invk);
        o[t + 256] = TAU_C * mr[t + 256] + om * (a1 * invk);
        o[t + 512] = TAU_C * mr[t + 512] + om * (a2 * invk);
        o[t + 768] = TAU_C * mr[t + 768] + om * (a3 * invk);
    }

    // block 0: final loss reduction
    if (j == 0 && writeLoss) {
        if (t < 128) lred[t] = g_loss_partial[t];
        __syncthreads();
        for (int s = 64; s > 0; s >>= 1) {
            if (t < s) lred[t] += lred[t + s];
            __syncthreads();
        }
        if (t == 0) out[0] = lred[0] * (1.f / (float)N_ROWS);
    }
}

// ---------------- entry ----------------
extern "C" void kernel_launch(void* const* d_in, const int* in_sizes, int n_in,
                              void* d_out, int out_size) {
    const float* z = (const float*)d_in[0];
    const float* M = (const float*)d_in[1];
    const int*   y = (const int*)d_in[2];
    float* out = (float*)d_out;

    int moff, writeM, writeLoss;
    if (out_size >= N_MOTIF * HDIM + 1)  { moff = 1; writeM = 1; writeLoss = 1; }
    else if (out_size >= N_MOTIF * HDIM) { moff = 0; writeM = 1; writeLoss = 0; }
    else                                 { moff = 0; writeM = 0; writeLoss = 1; }

    cudaFuncSetAttribute(k_gemm, cudaFuncAttributeMaxDynamicSharedMemorySize, SMEMB);

    k_gemm<<<128, 512, SMEMB>>>(z, M, y);
    k_topk<<<N_MOTIF, 256>>>(z, M, out, moff, writeM, writeLoss);
}

// round 6
// speedup vs baseline: 1.7618x; 1.0410x over previous
#include <cuda_runtime.h>
#include <cuda_bf16.h>
#include <cstdint>

#define N_ROWS   32768
#define HDIM     1024
#define N_MOTIF  128
#define N_CLASS  16
#define K2       32
#define EPS_C    1e-4f
#define TAU_C    0.99f

#define NTILES   256
#define SPT      32
#define SPC      (NTILES * SPT)

// ---------------- device scratch ----------------
__device__ float g_cval[(size_t)N_CLASS * 8 * SPC];
__device__ int   g_cidx[(size_t)N_CLASS * SPC];
__device__ int   g_bcnt[N_CLASS * NTILES];
__device__ float g_loss_partial[128];

#define NEG_INF __int_as_float(0xff800000)

__device__ __forceinline__ uint32_t smem_u32(const void* p) {
    uint32_t a;
    asm("{ .reg .u64 t; cvta.to.shared.u64 t, %1; cvt.u32.u64 %0, t; }" : "=r"(a) : "l"(p));
    return a;
}
__device__ __forceinline__ float rcp_newton(float x) {
    float y = __uint_as_float(0x7EF311C3u - __float_as_uint(x));
    y = y * fmaf(-x, y, 2.f);
    y = y * fmaf(-x, y, 2.f);
    y = y * fmaf(-x, y, 2.f);
    return y;
}
__device__ __forceinline__ uint32_t f2bf2(float lo, float hi) {
    __nv_bfloat162 h = __floats2bfloat162_rn(lo, hi);
    return *(uint32_t*)&h;
}
#define LDSM_X4(r0, r1, r2, r3, addr) \
    asm volatile("ldmatrix.sync.aligned.m8n8.x4.shared.b16 {%0,%1,%2,%3}, [%4];" \
        : "=r"(r0), "=r"(r1), "=r"(r2), "=r"(r3) : "r"(addr))

// ---------------- smem layout for k_gemm ----------------
#define KC      32
#define KP      40          // 80B row stride: ldmatrix phases conflict-free
#define XPS     129
#define SM_AB   0           // 2 bufs x 256 rows x 40 bf16 = 40960 B (union with XP)
#define SM_XP   0           // 128 x 129 f32 = 66048 B
#define SM_P    66048
#define SM_YC   (SM_P)
#define SM_ZN   (SM_P + 512)
#define SM_MN   (SM_P + 1024)
#define SM_PM   (SM_P + 1536)
#define SM_NS   (SM_P + 3584)
#define SM_LOSS (SM_P + 5632)
#define SM_SCNT (SM_P + 6144)
#define SM_MISC (SM_P + 6208)
#define SMEMB   (SM_P + 6272)

// ---------------- fused GEMM + distance + loss + candidate emit ----------------
__global__ __launch_bounds__(512, 1)
void k_gemm(const float* __restrict__ z, const float* __restrict__ Mv,
            const int* __restrict__ yraw) {
    extern __shared__ char dsm[];
    __nv_bfloat16 (*sAB)[256][KP] = (__nv_bfloat16(*)[256][KP])(dsm + SM_AB);
    float (*xp)[XPS]   = (float(*)[XPS])(dsm + SM_XP);
    int*   yc_s  = (int*)  (dsm + SM_YC);
    float* zn_s  = (float*)(dsm + SM_ZN);
    float* mn_s  = (float*)(dsm + SM_MN);
    float* pm_s  = (float*)(dsm + SM_PM);
    float* ns_s  = (float*)(dsm + SM_NS);
    float* loss_s= (float*)(dsm + SM_LOSS);
    int*   scnt  = (int*)  (dsm + SM_SCNT);
    float* blk_loss = (float*)(dsm + SM_MISC);
    int*   is64p    = (int*)  (dsm + SM_MISC + 4);

    const int t    = threadIdx.x;
    const int lane = t & 31;
    const int w    = t >> 5;
    const int wm   = w >> 2;
    const int wn   = w & 3;

    const int srow = t >> 1;
    const int half = t & 1;
    const bool isZ = (srow < 128);

    if (t == 0) {
        *blk_loss = 0.f;
        int f = 1;
        for (int i = 0; i < 32; i++)
            if (yraw[2 * i + 1] != 0) { f = 0; break; }
        *is64p = f;
    }

    uint32_t aAddr[2][2], bAddr[2][2];
    {
        int arow = wm * 32 + (lane & 15);
        int acol = (lane < 16) ? 0 : 8;
        int g    = lane >> 3;
        int bk   = (g & 1) * 8;
        int bnb  = (g >= 2) ? 8 : 0;
#pragma unroll
        for (int buf = 0; buf < 2; buf++) {
            aAddr[buf][0] = smem_u32(&sAB[buf][arow][acol]);
            aAddr[buf][1] = smem_u32(&sAB[buf][arow + 16][acol]);
#pragma unroll
            for (int pair = 0; pair < 2; pair++) {
                int n = wn * 32 + pair * 16 + bnb + (lane & 7);
                bAddr[buf][pair] = smem_u32(&sAB[buf][128 + n][bk]);
            }
        }
    }
    __syncthreads();
    const int is64 = *is64p;

    for (int tile = 0; tile < 2; tile++) {
        const int tileIdx = blockIdx.x + tile * 128;
        const int r0 = tileIdx * 128;

        __syncthreads();
        if (t < 16)  scnt[t] = 0;
        if (t < 128) yc_s[t] = is64 ? yraw[2 * (r0 + t)] : yraw[r0 + t];

        const float* src = isZ ? (z  + (size_t)(r0 + srow) * HDIM + half * 16)
                               : (Mv + (size_t)(srow - 128) * HDIM + half * 16);

        float acc[2][4][4];
#pragma unroll
        for (int a = 0; a < 2; a++)
#pragma unroll
            for (int b = 0; b < 4; b++)
#pragma unroll
                for (int c = 0; c < 4; c++) acc[a][b][c] = 0.f;
        float sq = 0.f;

        // prologue: chunk 0 -> buf 0 (16 floats per thread)
        float4 v[4];
#pragma unroll
        for (int j = 0; j < 4; j++) v[j] = *(const float4*)(src + 4 * j);
        {
#pragma unroll
            for (int j = 0; j < 4; j++) {
                sq = fmaf(v[j].x, v[j].x, sq); sq = fmaf(v[j].y, v[j].y, sq);
                sq = fmaf(v[j].z, v[j].z, sq); sq = fmaf(v[j].w, v[j].w, sq);
            }
            uint4 u0, u1;
            u0.x = f2bf2(v[0].x, v[0].y); u0.y = f2bf2(v[0].z, v[0].w);
            u0.z = f2bf2(v[1].x, v[1].y); u0.w = f2bf2(v[1].z, v[1].w);
            u1.x = f2bf2(v[2].x, v[2].y); u1.y = f2bf2(v[2].z, v[2].w);
            u1.z = f2bf2(v[3].x, v[3].y); u1.w = f2bf2(v[3].z, v[3].w);
            *(uint4*)&sAB[0][srow][half * 16]     = u0;
            *(uint4*)&sAB[0][srow][half * 16 + 8] = u1;
        }

        for (int ch = 0; ch < 32; ch++) {
            const int buf = ch & 1;
            __syncthreads();

            if (ch < 31) {
                const float* s2 = src + (ch + 1) * KC;
#pragma unroll
                for (int j = 0; j < 4; j++) v[j] = *(const float4*)(s2 + 4 * j);
            }

#pragma unroll
            for (int ks = 0; ks < 2; ks++) {
                uint32_t af[2][4];
                LDSM_X4(af[0][0], af[0][1], af[0][2], af[0][3], aAddr[buf][0] + ks * 32);
                LDSM_X4(af[1][0], af[1][1], af[1][2], af[1][3], aAddr[buf][1] + ks * 32);
                uint32_t bf[4][2];
                LDSM_X4(bf[0][0], bf[0][1], bf[1][0], bf[1][1], bAddr[buf][0] + ks * 32);
                LDSM_X4(bf[2][0], bf[2][1], bf[3][0], bf[3][1], bAddr[buf][1] + ks * 32);
#pragma unroll
                for (int mt = 0; mt < 2; mt++)
#pragma unroll
                    for (int nt = 0; nt < 4; nt++) {
                        asm volatile(
                            "mma.sync.aligned.m16n8k16.row.col.f32.bf16.bf16.f32 "
                            "{%0,%1,%2,%3},{%4,%5,%6,%7},{%8,%9},{%0,%1,%2,%3};"
                            : "+f"(acc[mt][nt][0]), "+f"(acc[mt][nt][1]),
                              "+f"(acc[mt][nt][2]), "+f"(acc[mt][nt][3])
                            : "r"(af[mt][0]), "r"(af[mt][1]), "r"(af[mt][2]), "r"(af[mt][3]),
                              "r"(bf[nt][0]), "r"(bf[nt][1]));
                    }
            }

            if (ch < 31) {
#pragma unroll
                for (int j = 0; j < 4; j++) {
                    sq = fmaf(v[j].x, v[j].x, sq); sq = fmaf(v[j].y, v[j].y, sq);
                    sq = fmaf(v[j].z, v[j].z, sq); sq = fmaf(v[j].w, v[j].w, sq);
                }
                uint4 u0, u1;
                u0.x = f2bf2(v[0].x, v[0].y); u0.y = f2bf2(v[0].z, v[0].w);
                u0.z = f2bf2(v[1].x, v[1].y); u0.w = f2bf2(v[1].z, v[1].w);
                u1.x = f2bf2(v[2].x, v[2].y); u1.y = f2bf2(v[2].z, v[2].w);
                u1.z = f2bf2(v[3].x, v[3].y); u1.w = f2bf2(v[3].z, v[3].w);
                const int nb = buf ^ 1;
                *(uint4*)&sAB[nb][srow][half * 16]     = u0;
                *(uint4*)&sAB[nb][srow][half * 16 + 8] = u1;
            }
        }

        // row norms
        {
            float o = __shfl_xor_sync(0xffffffffu, sq, 1);
            float tot = sq + o;
            if (half == 0) {
                if (isZ) zn_s[srow] = tot;
                else     mn_s[srow - 128] = tot;
            }
        }
        __syncthreads();

        // stage acc -> xp
        {
            const int rA = lane >> 2;
#pragma unroll
            for (int mt = 0; mt < 2; mt++)
#pragma unroll
                for (int nt = 0; nt < 4; nt++)
#pragma unroll
                    for (int r = 0; r < 4; r++) {
                        int row = wm * 32 + mt * 16 + rA + 8 * (r >> 1);
                        int col = wn * 32 + nt * 8 + 2 * (lane & 3) + (r & 1);
                        xp[row][col] = acc[mt][nt][r];
                    }
        }
        __syncthreads();

        // stats + candidate emit
        {
            const int row = t & 127;
            const int q   = t >> 7;
            const int c   = yc_s[row];
            const float znv = zn_s[row];
            float pmax = NEG_INF, nsum = 0.f;
#pragma unroll 8
            for (int i = 0; i < 32; i++) {
                int col = q * 32 + i;
                float d  = fmaf(-2.f, xp[row][col], znv + mn_s[col]);
                float x  = d + EPS_C;
                float dl = (1.f - EPS_C) * rcp_newton(x);
                float rr = 1.f + dl;
                float r2 = rr * rr;
                float s  = r2 * r2 * rr;
                if ((col >> 3) == c) pmax = fmaxf(pmax, s);
                else nsum += s;
            }
            pm_s[q * 128 + row] = pmax;
            ns_s[q * 128 + row] = nsum;

            if (q == 0) {
                int rank = atomicAdd(&scnt[c], 1);
                if (rank < SPT) {
                    int slot = tileIdx * SPT + rank;
                    g_cidx[c * SPC + slot] = r0 + row;
#pragma unroll
                    for (int m = 0; m < 8; m++) {
                        int col = 8 * c + m;
                        float d = fmaf(-2.f, xp[row][col], znv + mn_s[col]);
                        g_cval[(size_t)((c << 3) + m) * SPC + slot] = d;
                    }
                }
            }
        }
        __syncthreads();

        if (t < 128) {
            float P = fmaxf(fmaxf(pm_s[t], pm_s[128 + t]),
                            fmaxf(pm_s[256 + t], pm_s[384 + t]));
            float S = (ns_s[t] + ns_s[128 + t]) + (ns_s[256 + t] + ns_s[384 + t]);
            loss_s[t] = log1pf(S / P);
        }
        if (t < 16) g_bcnt[t * NTILES + tileIdx] = min(scnt[t], SPT);
        __syncthreads();
        for (int s = 64; s > 0; s >>= 1) {
            if (t < s) loss_s[t] += loss_s[t + s];
            __syncthreads();
        }
        if (t == 0) *blk_loss += loss_s[0];
    }

    if (t == 0) g_loss_partial[blockIdx.x] = *blk_loss;
}

// ---------------- top-k (cached local max) + motif update + loss ----------------
#define CAPC 2560
#define TKT  512

__global__ __launch_bounds__(TKT)
void k_topk(const float* __restrict__ z, const float* __restrict__ M,
            float* __restrict__ out, int moff, int writeM, int writeLoss) {
    __shared__ float sv[CAPC];
    __shared__ int   si[CAPC];
    __shared__ int   pre[256];
    __shared__ int   wsum[8], wscan[8];
    __shared__ float wv[16];
    __shared__ int   wi[16], wt_s[16];
    __shared__ int   gwin;
    __shared__ int   selIdx[K2];
    __shared__ float lred[128];
    __shared__ int   ntot;

    const int t    = threadIdx.x;
    const int lane = t & 31;
    const int w    = t >> 5;
    const int j    = blockIdx.x;
    const int c    = j >> 3;
    const int m    = j & 7;

    // segment counts + prefix sum over 256 tiles (threads 0..255)
    int cnt = 0;
    if (t < 256) {
        cnt = g_bcnt[c * NTILES + t];
        int v = cnt;
#pragma unroll
        for (int o = 1; o < 32; o <<= 1) {
            int nvv = __shfl_up_sync(0xffffffffu, v, o);
            if (lane >= o) v += nvv;
        }
        if (lane == 31) wsum[w] = v;
        pre[t] = v - cnt;   // intra-warp exclusive; warp base added below
    }
    __syncthreads();
    if (t < 8) {
        int s = wsum[t];
#pragma unroll
        for (int o = 1; o < 8; o <<= 1) {
            int nvv = __shfl_up_sync(0xffu, s, o);
            if ((t & 7) >= o) s += nvv;
        }
        wscan[t] = s;
    }
    __syncthreads();
    if (t < 256) {
        int excl = pre[t] + (w > 0 ? wscan[w - 1] : 0);
        pre[t] = excl;
        if (t == 255) ntot = min(excl + cnt, CAPC);
    }
    __syncthreads();

    // gather candidates into compact smem arrays (threads 0..255, one tile each)
    if (t < 256) {
        const float* cvp = g_cval + (size_t)((c << 3) + m) * SPC + t * SPT;
        const int*   cip = g_cidx + (size_t)c * SPC + t * SPT;
        int off = pre[t];
        for (int i = 0; i < cnt; i++) {
            if (off + i < CAPC) { sv[off + i] = cvp[i]; si[off + i] = cip[i]; }
        }
    }
    __syncthreads();
    const int n = ntot;

    // cached local best per thread
    float lv = NEG_INF; int li = 0x7fffffff; int lp = -1;
    for (int p = t; p < n; p += TKT) {
        float vv = sv[p]; int ii = si[p];
        if (vv > lv || (vv == lv && ii < li)) { lv = vv; li = ii; lp = p; }
    }

    // K2 extraction rounds: reduce cached bests; only winner rescans its segment
    for (int k = 0; k < K2; k++) {
        float bv = lv; int bi = li; int bt = t;
#pragma unroll
        for (int o = 16; o > 0; o >>= 1) {
            float ov = __shfl_xor_sync(0xffffffffu, bv, o);
            int   oi = __shfl_xor_sync(0xffffffffu, bi, o);
            int   ot = __shfl_xor_sync(0xffffffffu, bt, o);
            if (ov > bv || (ov == bv && oi < bi)) { bv = ov; bi = oi; bt = ot; }
        }
        if (lane == 0) { wv[w] = bv; wi[w] = bi; wt_s[w] = bt; }
        __syncthreads();
        if (t == 0) {
            float fv = wv[0]; int fi = wi[0]; int ft = wt_s[0];
            for (int q2 = 1; q2 < 16; q2++)
                if (wv[q2] > fv || (wv[q2] == fv && wi[q2] < fi)) { fv = wv[q2]; fi = wi[q2]; ft = wt_s[q2]; }
            selIdx[k] = (fv == NEG_INF) ? 0 : fi;
            gwin = ft;
        }
        __syncthreads();
        if (t == gwin) {
            if (lp >= 0) sv[lp] = NEG_INF;
            lv = NEG_INF; li = 0x7fffffff; lp = -1;
            for (int p = t; p < n; p += TKT) {
                float vv = sv[p]; int ii = si[p];
                if (vv > lv || (vv == lv && ii < li)) { lv = vv; li = ii; lp = p; }
            }
        }
    }
    __syncthreads();

    // gather-mean of K2 z-rows + EMA blend
    float a0 = 0.f, a1 = 0.f;
#pragma unroll 4
    for (int k = 0; k < K2; k++) {
        const float* zr = z + (size_t)selIdx[k] * HDIM;
        a0 += zr[t]; a1 += zr[t + TKT];
    }
    if (writeM) {
        const float* mr = M + (size_t)j * HDIM;
        float* o = out + moff + (size_t)j * HDIM;
        const float invk = 1.f / (float)K2;
        const float om = 1.f - TAU_C;
        o[t]       = TAU_C * mr[t]       + om * (a0 * invk);
        o[t + TKT] = TAU_C * mr[t + TKT] + om * (a1 * invk);
    }

    if (j == 0 && writeLoss) {
        if (t < 128) lred[t] = g_loss_partial[t];
        __syncthreads();
        for (int s = 64; s > 0; s >>= 1) {
            if (t < s) lred[t] += lred[t + s];
            __syncthreads();
        }
        if (t == 0) out[0] = lred[0] * (1.f / (float)N_ROWS);
    }
}

// ---------------- entry ----------------
extern "C" void kernel_launch(void* const* d_in, const int* in_sizes, int n_in,
                              void* d_out, int out_size) {
    const float* z = (const float*)d_in[0];
    const float* M = (const float*)d_in[1];
    const int*   y = (const int*)d_in[2];
    float* out = (float*)d_out;

    int moff, writeM, writeLoss;
    if (out_size >= N_MOTIF * HDIM + 1)  { moff = 1; writeM = 1; writeLoss = 1; }
    else if (out_size >= N_MOTIF * HDIM) { moff = 0; writeM = 1; writeLoss = 0; }
    else                                 { moff = 0; writeM = 0; writeLoss = 1; }

    cudaFuncSetAttribute(k_gemm, cudaFuncAttributeMaxDynamicSharedMemorySize, SMEMB);

    k_gemm<<<128, 512, SMEMB>>>(z, M, y);
    k_topk<<<N_MOTIF, TKT>>>(z, M, out, moff, writeM, writeLoss);
}

// round 7
// speedup vs baseline: 1.7628x; 1.0006x over previous
#include <cuda_runtime.h>
#include <cuda_bf16.h>
#include <cstdint>

#define N_ROWS   32768
#define HDIM     1024
#define N_MOTIF  128
#define N_CLASS  16
#define K2       32
#define EPS_C    1e-4f
#define TAU_C    0.99f

#define NTILES   256
#define SPT      32
#define SPC      (NTILES * SPT)

// ---------------- device scratch ----------------
__device__ float g_cval[(size_t)N_CLASS * 8 * SPC];
__device__ int   g_cidx[(size_t)N_CLASS * SPC];
__device__ int   g_bcnt[N_CLASS * NTILES];
__device__ float g_loss_partial[128];

#define NEG_INF __int_as_float(0xff800000)

__device__ __forceinline__ uint32_t smem_u32(const void* p) {
    uint32_t a;
    asm("{ .reg .u64 t; cvta.to.shared.u64 t, %1; cvt.u32.u64 %0, t; }" : "=r"(a) : "l"(p));
    return a;
}
__device__ __forceinline__ float rcp_newton(float x) {
    float y = __uint_as_float(0x7EF311C3u - __float_as_uint(x));
    y = y * fmaf(-x, y, 2.f);
    y = y * fmaf(-x, y, 2.f);
    y = y * fmaf(-x, y, 2.f);
    return y;
}
__device__ __forceinline__ uint32_t f2bf2(float lo, float hi) {
    __nv_bfloat162 h = __floats2bfloat162_rn(lo, hi);
    return *(uint32_t*)&h;
}
#define LDSM_X4(r0, r1, r2, r3, addr) \
    asm volatile("ldmatrix.sync.aligned.m8n8.x4.shared.b16 {%0,%1,%2,%3}, [%4];" \
        : "=r"(r0), "=r"(r1), "=r"(r2), "=r"(r3) : "r"(addr))

// ---------------- smem layout for k_gemm ----------------
#define KC      32
#define KP      40          // 80B row stride: ldmatrix phases conflict-free
#define XPS     129
#define SM_AB   0           // 2 bufs x 256 rows x 40 bf16 = 40960 B (union with XP)
#define SM_XP   0           // 128 x 129 f32 = 66048 B
#define SM_P    66048
#define SM_YC   (SM_P)
#define SM_ZN   (SM_P + 512)
#define SM_MN   (SM_P + 1024)
#define SM_PM   (SM_P + 1536)
#define SM_NS   (SM_P + 3584)
#define SM_LOSS (SM_P + 5632)
#define SM_SCNT (SM_P + 6144)
#define SM_MISC (SM_P + 6208)
#define SMEMB   (SM_P + 6272)

// ---------------- fused GEMM + distance + loss + candidate emit ----------------
__global__ __launch_bounds__(512, 1)
void k_gemm(const float* __restrict__ z, const float* __restrict__ Mv,
            const int* __restrict__ yraw) {
    extern __shared__ char dsm[];
    __nv_bfloat16 (*sAB)[256][KP] = (__nv_bfloat16(*)[256][KP])(dsm + SM_AB);
    float (*xp)[XPS]   = (float(*)[XPS])(dsm + SM_XP);
    int*   yc_s  = (int*)  (dsm + SM_YC);
    float* zn_s  = (float*)(dsm + SM_ZN);
    float* mn_s  = (float*)(dsm + SM_MN);
    float* pm_s  = (float*)(dsm + SM_PM);
    float* ns_s  = (float*)(dsm + SM_NS);
    float* loss_s= (float*)(dsm + SM_LOSS);
    int*   scnt  = (int*)  (dsm + SM_SCNT);
    float* blk_loss = (float*)(dsm + SM_MISC);
    int*   is64p    = (int*)  (dsm + SM_MISC + 4);

    const int t    = threadIdx.x;
    const int lane = t & 31;
    const int w    = t >> 5;
    const int wm   = w >> 2;
    const int wn   = w & 3;

    const int srow = t >> 1;
    const int half = t & 1;
    const bool isZ = (srow < 128);

    if (t == 0) {
        *blk_loss = 0.f;
        int f = 1;
        for (int i = 0; i < 32; i++)
            if (yraw[2 * i + 1] != 0) { f = 0; break; }
        *is64p = f;
    }

    uint32_t aAddr[2][2], bAddr[2][2];
    {
        int arow = wm * 32 + (lane & 15);
        int acol = (lane < 16) ? 0 : 8;
        int g    = lane >> 3;
        int bk   = (g & 1) * 8;
        int bnb  = (g >= 2) ? 8 : 0;
#pragma unroll
        for (int buf = 0; buf < 2; buf++) {
            aAddr[buf][0] = smem_u32(&sAB[buf][arow][acol]);
            aAddr[buf][1] = smem_u32(&sAB[buf][arow + 16][acol]);
#pragma unroll
            for (int pair = 0; pair < 2; pair++) {
                int n = wn * 32 + pair * 16 + bnb + (lane & 7);
                bAddr[buf][pair] = smem_u32(&sAB[buf][128 + n][bk]);
            }
        }
    }
    __syncthreads();
    const int is64 = *is64p;

    for (int tile = 0; tile < 2; tile++) {
        const int tileIdx = blockIdx.x + tile * 128;
        const int r0 = tileIdx * 128;

        __syncthreads();
        if (t < 16)  scnt[t] = 0;
        if (t < 128) yc_s[t] = is64 ? yraw[2 * (r0 + t)] : yraw[r0 + t];

        const float* src = isZ ? (z  + (size_t)(r0 + srow) * HDIM + half * 16)
                               : (Mv + (size_t)(srow - 128) * HDIM + half * 16);

        float acc[2][4][4];
#pragma unroll
        for (int a = 0; a < 2; a++)
#pragma unroll
            for (int b = 0; b < 4; b++)
#pragma unroll
                for (int c = 0; c < 4; c++) acc[a][b][c] = 0.f;
        float sq = 0.f;

        // prologue: chunk 0 -> buf 0 (16 floats per thread)
        float4 v[4];
#pragma unroll
        for (int j = 0; j < 4; j++) v[j] = *(const float4*)(src + 4 * j);
        {
#pragma unroll
            for (int j = 0; j < 4; j++) {
                sq = fmaf(v[j].x, v[j].x, sq); sq = fmaf(v[j].y, v[j].y, sq);
                sq = fmaf(v[j].z, v[j].z, sq); sq = fmaf(v[j].w, v[j].w, sq);
            }
            uint4 u0, u1;
            u0.x = f2bf2(v[0].x, v[0].y); u0.y = f2bf2(v[0].z, v[0].w);
            u0.z = f2bf2(v[1].x, v[1].y); u0.w = f2bf2(v[1].z, v[1].w);
            u1.x = f2bf2(v[2].x, v[2].y); u1.y = f2bf2(v[2].z, v[2].w);
            u1.z = f2bf2(v[3].x, v[3].y); u1.w = f2bf2(v[3].z, v[3].w);
            *(uint4*)&sAB[0][srow][half * 16]     = u0;
            *(uint4*)&sAB[0][srow][half * 16 + 8] = u1;
        }

        for (int ch = 0; ch < 32; ch++) {
            const int buf = ch & 1;
            __syncthreads();

            if (ch < 31) {
                const float* s2 = src + (ch + 1) * KC;
#pragma unroll
                for (int j = 0; j < 4; j++) v[j] = *(const float4*)(s2 + 4 * j);
            }

#pragma unroll
            for (int ks = 0; ks < 2; ks++) {
                uint32_t af[2][4];
                LDSM_X4(af[0][0], af[0][1], af[0][2], af[0][3], aAddr[buf][0] + ks * 32);
                LDSM_X4(af[1][0], af[1][1], af[1][2], af[1][3], aAddr[buf][1] + ks * 32);
                uint32_t bf[4][2];
                LDSM_X4(bf[0][0], bf[0][1], bf[1][0], bf[1][1], bAddr[buf][0] + ks * 32);
                LDSM_X4(bf[2][0], bf[2][1], bf[3][0], bf[3][1], bAddr[buf][1] + ks * 32);
#pragma unroll
                for (int mt = 0; mt < 2; mt++)
#pragma unroll
                    for (int nt = 0; nt < 4; nt++) {
                        asm volatile(
                            "mma.sync.aligned.m16n8k16.row.col.f32.bf16.bf16.f32 "
                            "{%0,%1,%2,%3},{%4,%5,%6,%7},{%8,%9},{%0,%1,%2,%3};"
                            : "+f"(acc[mt][nt][0]), "+f"(acc[mt][nt][1]),
                              "+f"(acc[mt][nt][2]), "+f"(acc[mt][nt][3])
                            : "r"(af[mt][0]), "r"(af[mt][1]), "r"(af[mt][2]), "r"(af[mt][3]),
                              "r"(bf[nt][0]), "r"(bf[nt][1]));
                    }
            }

            if (ch < 31) {
#pragma unroll
                for (int j = 0; j < 4; j++) {
                    sq = fmaf(v[j].x, v[j].x, sq); sq = fmaf(v[j].y, v[j].y, sq);
                    sq = fmaf(v[j].z, v[j].z, sq); sq = fmaf(v[j].w, v[j].w, sq);
                }
                uint4 u0, u1;
                u0.x = f2bf2(v[0].x, v[0].y); u0.y = f2bf2(v[0].z, v[0].w);
                u0.z = f2bf2(v[1].x, v[1].y); u0.w = f2bf2(v[1].z, v[1].w);
                u1.x = f2bf2(v[2].x, v[2].y); u1.y = f2bf2(v[2].z, v[2].w);
                u1.z = f2bf2(v[3].x, v[3].y); u1.w = f2bf2(v[3].z, v[3].w);
                const int nb = buf ^ 1;
                *(uint4*)&sAB[nb][srow][half * 16]     = u0;
                *(uint4*)&sAB[nb][srow][half * 16 + 8] = u1;
            }
        }

        // row norms
        {
            float o = __shfl_xor_sync(0xffffffffu, sq, 1);
            float tot = sq + o;
            if (half == 0) {
                if (isZ) zn_s[srow] = tot;
                else     mn_s[srow - 128] = tot;
            }
        }
        __syncthreads();

        // stage acc -> xp
        {
            const int rA = lane >> 2;
#pragma unroll
            for (int mt = 0; mt < 2; mt++)
#pragma unroll
                for (int nt = 0; nt < 4; nt++)
#pragma unroll
                    for (int r = 0; r < 4; r++) {
                        int row = wm * 32 + mt * 16 + rA + 8 * (r >> 1);
                        int col = wn * 32 + nt * 8 + 2 * (lane & 3) + (r & 1);
                        xp[row][col] = acc[mt][nt][r];
                    }
        }
        __syncthreads();

        // stats + candidate emit
        {
            const int row = t & 127;
            const int q   = t >> 7;
            const int c   = yc_s[row];
            const float znv = zn_s[row];
            float pmax = NEG_INF, nsum = 0.f;
#pragma unroll 8
            for (int i = 0; i < 32; i++) {
                int col = q * 32 + i;
                float d  = fmaf(-2.f, xp[row][col], znv + mn_s[col]);
                float x  = d + EPS_C;
                float dl = (1.f - EPS_C) * rcp_newton(x);
                float rr = 1.f + dl;
                float r2 = rr * rr;
                float s  = r2 * r2 * rr;
                if ((col >> 3) == c) pmax = fmaxf(pmax, s);
                else nsum += s;
            }
            pm_s[q * 128 + row] = pmax;
            ns_s[q * 128 + row] = nsum;

            if (q == 0) {
                int rank = atomicAdd(&scnt[c], 1);
                if (rank < SPT) {
                    int slot = tileIdx * SPT + rank;
                    g_cidx[c * SPC + slot] = r0 + row;
#pragma unroll
                    for (int m = 0; m < 8; m++) {
                        int col = 8 * c + m;
                        float d = fmaf(-2.f, xp[row][col], znv + mn_s[col]);
                        g_cval[(size_t)((c << 3) + m) * SPC + slot] = d;
                    }
                }
            }
        }
        __syncthreads();

        if (t < 128) {
            float P = fmaxf(fmaxf(pm_s[t], pm_s[128 + t]),
                            fmaxf(pm_s[256 + t], pm_s[384 + t]));
            float S = (ns_s[t] + ns_s[128 + t]) + (ns_s[256 + t] + ns_s[384 + t]);
            loss_s[t] = log1pf(S / P);
        }
        if (t < 16) g_bcnt[t * NTILES + tileIdx] = min(scnt[t], SPT);
        __syncthreads();
        for (int s = 64; s > 0; s >>= 1) {
            if (t < s) loss_s[t] += loss_s[t + s];
            __syncthreads();
        }
        if (t == 0) *blk_loss += loss_s[0];
    }

    if (t == 0) g_loss_partial[blockIdx.x] = *blk_loss;
}

// ---------------- top-k (cached local max) + motif update + loss ----------------
#define CAPC 2560
#define TKT  512

__global__ __launch_bounds__(TKT)
void k_topk(const float* __restrict__ z, const float* __restrict__ M,
            float* __restrict__ out, int moff, int writeM, int writeLoss) {
    __shared__ float sv[CAPC];
    __shared__ int   si[CAPC];
    __shared__ int   pre[256];
    __shared__ int   wsum[8], wscan[8];
    __shared__ float wv[16];
    __shared__ int   wi[16], wt_s[16];
    __shared__ int   gwin;
    __shared__ int   selIdx[K2];
    __shared__ float lred[128];
    __shared__ int   ntot;

    const int t    = threadIdx.x;
    const int lane = t & 31;
    const int w    = t >> 5;
    const int j    = blockIdx.x;
    const int c    = j >> 3;
    const int m    = j & 7;

    // segment counts + prefix sum over 256 tiles (threads 0..255)
    int cnt = 0;
    if (t < 256) {
        cnt = g_bcnt[c * NTILES + t];
        int v = cnt;
#pragma unroll
        for (int o = 1; o < 32; o <<= 1) {
            int nvv = __shfl_up_sync(0xffffffffu, v, o);
            if (lane >= o) v += nvv;
        }
        if (lane == 31) wsum[w] = v;
        pre[t] = v - cnt;   // intra-warp exclusive; warp base added below
    }
    __syncthreads();
    if (t < 8) {
        int s = wsum[t];
#pragma unroll
        for (int o = 1; o < 8; o <<= 1) {
            int nvv = __shfl_up_sync(0xffu, s, o);
            if ((t & 7) >= o) s += nvv;
        }
        wscan[t] = s;
    }
    __syncthreads();
    if (t < 256) {
        int excl = pre[t] + (w > 0 ? wscan[w - 1] : 0);
        pre[t] = excl;
        if (t == 255) ntot = min(excl + cnt, CAPC);
    }
    __syncthreads();

    // gather candidates into compact smem arrays (threads 0..255, one tile each)
    if (t < 256) {
        const float* cvp = g_cval + (size_t)((c << 3) + m) * SPC + t * SPT;
        const int*   cip = g_cidx + (size_t)c * SPC + t * SPT;
        int off = pre[t];
        for (int i = 0; i < cnt; i++) {
            if (off + i < CAPC) { sv[off + i] = cvp[i]; si[off + i] = cip[i]; }
        }
    }
    __syncthreads();
    const int n = ntot;

    // cached local best per thread
    float lv = NEG_INF; int li = 0x7fffffff; int lp = -1;
    for (int p = t; p < n; p += TKT) {
        float vv = sv[p]; int ii = si[p];
        if (vv > lv || (vv == lv && ii < li)) { lv = vv; li = ii; lp = p; }
    }

    // K2 extraction rounds: reduce cached bests; only winner rescans its segment
    for (int k = 0; k < K2; k++) {
        float bv = lv; int bi = li; int bt = t;
#pragma unroll
        for (int o = 16; o > 0; o >>= 1) {
            float ov = __shfl_xor_sync(0xffffffffu, bv, o);
            int   oi = __shfl_xor_sync(0xffffffffu, bi, o);
            int   ot = __shfl_xor_sync(0xffffffffu, bt, o);
            if (ov > bv || (ov == bv && oi < bi)) { bv = ov; bi = oi; bt = ot; }
        }
        if (lane == 0) { wv[w] = bv; wi[w] = bi; wt_s[w] = bt; }
        __syncthreads();
        if (t == 0) {
            float fv = wv[0]; int fi = wi[0]; int ft = wt_s[0];
            for (int q2 = 1; q2 < 16; q2++)
                if (wv[q2] > fv || (wv[q2] == fv && wi[q2] < fi)) { fv = wv[q2]; fi = wi[q2]; ft = wt_s[q2]; }
            selIdx[k] = (fv == NEG_INF) ? 0 : fi;
            gwin = ft;
        }
        __syncthreads();
        if (t == gwin) {
            if (lp >= 0) sv[lp] = NEG_INF;
            lv = NEG_INF; li = 0x7fffffff; lp = -1;
            for (int p = t; p < n; p += TKT) {
                float vv = sv[p]; int ii = si[p];
                if (vv > lv || (vv == lv && ii < li)) { lv = vv; li = ii; lp = p; }
            }
        }
    }
    __syncthreads();

    // gather-mean of K2 z-rows + EMA blend
    float a0 = 0.f, a1 = 0.f;
#pragma unroll 4
    for (int k = 0; k < K2; k++) {
        const float* zr = z + (size_t)selIdx[k] * HDIM;
        a0 += zr[t]; a1 += zr[t + TKT];
    }
    if (writeM) {
        const float* mr = M + (size_t)j * HDIM;
        float* o = out + moff + (size_t)j * HDIM;
        const float invk = 1.f / (float)K2;
        const float om = 1.f - TAU_C;
        o[t]       = TAU_C * mr[t]       + om * (a0 * invk);
        o[t + TKT] = TAU_C * mr[t + TKT] + om * (a1 * invk);
    }

    if (j == 0 && writeLoss) {
        if (t < 128) lred[t] = g_loss_partial[t];
        __syncthreads();
        for (int s = 64; s > 0; s >>= 1) {
            if (t < s) lred[t] += lred[t + s];
            __syncthreads();
        }
        if (t == 0) out[0] = lred[0] * (1.f / (float)N_ROWS);
    }
}

// ---------------- entry ----------------
extern "C" void kernel_launch(void* const* d_in, const int* in_sizes, int n_in,
                              void* d_out, int out_size) {
    const float* z = (const float*)d_in[0];
    const float* M = (const float*)d_in[1];
    const int*   y = (const int*)d_in[2];
    float* out = (float*)d_out;

    int moff, writeM, writeLoss;
    if (out_size >= N_MOTIF * HDIM + 1)  { moff = 1; writeM = 1; writeLoss = 1; }
    else if (out_size >= N_MOTIF * HDIM) { moff = 0; writeM = 1; writeLoss = 0; }
    else                                 { moff = 0; writeM = 0; writeLoss = 1; }

    cudaFuncSetAttribute(k_gemm, cudaFuncAttributeMaxDynamicSharedMemorySize, SMEMB);

    k_gemm<<<128, 512, SMEMB>>>(z, M, y);
    k_topk<<<N_MOTIF, TKT>>>(z, M, out, moff, writeM, writeLoss);
}